// round 17
// baseline (speedup 1.0000x reference)
#include <cuda_runtime.h>
#include <cuda_fp16.h>

// Problem constants
static constexpr int LD  = 4;       // LOCAL_DIM
static constexpr int MD  = 64;      // M
static constexpr int TRI = 89440;   // sum_{k=1..64} k^2

// epsilon strides (elements): shape (4, 64, 64, 65, 65) = (d, m, l, u, dn)
static constexpr unsigned long long SD = 17305600ull; // 64*64*65*65
static constexpr unsigned long long SM = 270400ull;   // 64*65*65
static constexpr unsigned long long SL = 4225ull;     // 65*65

static constexpr int NGROUP = 256;  // batch groups for the range pass

// Scratch: fp16 LOG2 of the realized region, layout [d][loff(l)+u*(l+1)+dn][m/2]
__device__ __half2 g_scratch2[(size_t)LD * TRI * (MD / 2)];

// Per-group range partials (plain stores; no global atomics) and final ranges.
// Entry layout (1024 ints): [metric 0..3][d 0..3][l 0..63];
// metric 0 = max u, 1 = max(63-u), 2 = max dn, 3 = max(63-dn).
__device__ int g_part[NGROUP][1024];
__device__ int g_rng[4][LD][64];

__device__ __host__ __forceinline__ int loff(int l) {
    return l * (l + 1) * (2 * l + 1) / 6;
}

// Per-warp dtype detection (int64 vs int32 indices; values < 4).
__device__ __forceinline__ bool detect_is64(const void* raw, int lane) {
    unsigned wodd = ((const unsigned*)raw)[2 * lane + 1];
    return __ballot_sync(0xffffffffu, wodd != 0u) == 0u;
}

__device__ __forceinline__ int load_idx(const void* raw, size_t pos, bool is64) {
    if (is64) return (int)((const long long*)raw)[pos];
    return ((const int*)raw)[pos];
}

// ---------------------------------------------------------------------------
// Kernel 1: per-group (u,dn) range partials (unchanged from R15).
// ---------------------------------------------------------------------------
__global__ void __launch_bounds__(256) mark_partial(const void* __restrict__ raw) {
    const int t     = threadIdx.x;
    const int w     = t >> 5;
    const int lane  = t & 31;
    const int group = blockIdx.x;          // 0..255

    __shared__ int s_rng[4][LD][64];       // 4 KB
    for (int i = t; i < 1024; i += 256)
        (&s_rng[0][0][0])[i] = 0;
    const bool is64 = detect_is64(raw, lane);
    __syncthreads();

    int i0[4], i1[4];
    #pragma unroll
    for (int p = 0; p < 4; ++p) {
        const size_t base = ((size_t)(group * 32 + w * 4 + p)) * 64;
        i0[p] = load_idx(raw, base + lane,      is64);
        i1[p] = load_idx(raw, base + lane + 32, is64);
    }

    const unsigned lm = (1u << lane) - 1u;
    #pragma unroll
    for (int p = 0; p < 4; ++p) {
        const unsigned m0lo = __ballot_sync(0xffffffffu, i0[p] & 1);
        const unsigned m1lo = __ballot_sync(0xffffffffu, i0[p] & 2);
        const unsigned m0hi = __ballot_sync(0xffffffffu, i1[p] & 1);
        const unsigned m1hi = __ballot_sync(0xffffffffu, i1[p] & 2);

        const int u_lo  = __popc(m0lo & lm);
        const int dn_lo = __popc(m1lo & lm);
        const int u_hi  = __popc(m0lo) + __popc(m0hi & lm);
        const int dn_hi = __popc(m1lo) + __popc(m1hi & lm);

        atomicMax(&s_rng[0][i0[p]][lane],      u_lo);
        atomicMax(&s_rng[1][i0[p]][lane],      63 - u_lo);
        atomicMax(&s_rng[2][i0[p]][lane],      dn_lo);
        atomicMax(&s_rng[3][i0[p]][lane],      63 - dn_lo);
        atomicMax(&s_rng[0][i1[p]][lane + 32], u_hi);
        atomicMax(&s_rng[1][i1[p]][lane + 32], 63 - u_hi);
        atomicMax(&s_rng[2][i1[p]][lane + 32], dn_hi);
        atomicMax(&s_rng[3][i1[p]][lane + 32], 63 - dn_hi);
    }
    __syncthreads();

    #pragma unroll
    for (int k = 0; k < 4; ++k) {
        const int i = t + 256 * k;
        g_part[group][i] = (&s_rng[0][0][0])[i];
    }
}

// ---------------------------------------------------------------------------
// Kernel 1b: reduce 256 partials -> g_rng (unchanged from R15).
// ---------------------------------------------------------------------------
__global__ void __launch_bounds__(256) reduce_rng() {
    const int t       = threadIdx.x;
    const int e_local = t & 15;
    const int grp     = t >> 4;
    const int entry   = blockIdx.x * 16 + e_local;

    int v = 0;
    #pragma unroll
    for (int k = 0; k < 16; ++k)
        v = max(v, g_part[grp * 16 + k][entry]);

    __shared__ int s[16][17];
    s[e_local][grp] = v;
    __syncthreads();
    if (t < 16) {
        int m = 0;
        #pragma unroll
        for (int g = 0; g < 16; ++g) m = max(m, s[t][g]);
        (&g_rng[0][0][0])[blockIdx.x * 16 + t] = m;
    }
}

// ---------------------------------------------------------------------------
// Kernel 2: transpose eps -> log2-fp16 scratch, realized rectangle, u-pair
// per block (unchanged from R15). block (32,8); grid (64, 32, 4).
// ---------------------------------------------------------------------------
__global__ void __launch_bounds__(256) eps_transpose(const float* __restrict__ eps) {
    const int l  = blockIdx.x;
    const int u0 = 2 * blockIdx.y;
    const int u1 = u0 + 1;
    const int d  = blockIdx.z;

    const int umax = g_rng[0][d][l];
    const int umin = 63 - g_rng[1][d][l];
    const bool v0 = (u0 >= umin) && (u0 <= umax);
    const bool v1 = (u1 >= umin) && (u1 <= umax);
    if (!v0 && !v1) return;
    const int dn1 = g_rng[2][d][l];
    const int dn0 = 63 - g_rng[3][d][l];
    if (dn0 > dn1) return;
    const int W = dn1 - dn0;

    const int tx = threadIdx.x;
    const int ty = threadIdx.y;

    __shared__ float tile[2][64][65];

    const size_t inA = (size_t)d * SD + (size_t)l * SL + (size_t)u0 * 65ull + dn0;
    const size_t inB = inA + 65ull;
    if (W < 32) {
        #pragma unroll
        for (int m = ty; m < 64; m += 8) {
            const size_t rA = inA + (size_t)m * SM;
            const size_t rB = inB + (size_t)m * SM;
            if (v0 && tx <= W) tile[0][m][tx] = __log2f(eps[rA + tx]);
            if (v1 && tx <= W) tile[1][m][tx] = __log2f(eps[rB + tx]);
        }
    } else {
        #pragma unroll
        for (int m = ty; m < 64; m += 8) {
            const size_t rA = inA + (size_t)m * SM;
            const size_t rB = inB + (size_t)m * SM;
            if (v0) {
                tile[0][m][tx] = __log2f(eps[rA + tx]);
                if (tx + 32 <= W) tile[0][m][tx + 32] = __log2f(eps[rA + tx + 32]);
            }
            if (v1) {
                tile[1][m][tx] = __log2f(eps[rB + tx]);
                if (tx + 32 <= W) tile[1][m][tx + 32] = __log2f(eps[rB + tx + 32]);
            }
        }
    }
    __syncthreads();

    const size_t obA = ((size_t)d * TRI + (size_t)loff(l) + (size_t)u0 * (l + 1)) * 32ull;
    const size_t obB = obA + (size_t)(l + 1) * 32ull;
    for (int dn = dn0 + ty; dn <= dn1; dn += 8) {
        const int c = dn - dn0;
        if (v0) g_scratch2[obA + (size_t)dn * 32ull + tx] =
            __floats2half2_rn(tile[0][2 * tx][c], tile[0][2 * tx + 1][c]);
        if (v1) g_scratch2[obB + (size_t)dn * 32ull + tx] =
            __floats2half2_rn(tile[1][2 * tx][c], tile[1][2 * tx + 1][c]);
    }
}

// ---------------------------------------------------------------------------
// Kernel 3: warp-per-batch compute, VECTORIZED. Lane = (site-group g = lane>>3,
// m-octet o = lane&7). 16 x LDG.128 per lane (8 halfs = m 8o..8o+7) over its
// 16 sites (site = 4k + g). Reduce: xor-shuffle over site groups (8,16), exp2,
// butterfly over octets (1,2,4).
// ---------------------------------------------------------------------------
__global__ void __launch_bounds__(256) seggps_compute(const void* __restrict__ raw,
                                                      float* __restrict__ out) {
    __shared__ unsigned s_base[8][64];

    const int t    = threadIdx.x;
    const int w    = t >> 5;
    const int lane = t & 31;
    const int b    = blockIdx.x * 8 + w;

    // ---- scan (unchanged): lane owns sites (lane, lane+32) ----
    const bool is64 = detect_is64(raw, lane);
    const size_t base = (size_t)b * 64;
    const int i0 = load_idx(raw, base + lane,      is64);
    const int i1 = load_idx(raw, base + lane + 32, is64);

    const unsigned m0lo = __ballot_sync(0xffffffffu, i0 & 1);
    const unsigned m1lo = __ballot_sync(0xffffffffu, i0 & 2);
    const unsigned m0hi = __ballot_sync(0xffffffffu, i1 & 1);
    const unsigned m1hi = __ballot_sync(0xffffffffu, i1 & 2);

    const unsigned lm = (1u << lane) - 1u;
    const int u_lo  = __popc(m0lo & lm);
    const int dn_lo = __popc(m1lo & lm);
    const int u_hi  = __popc(m0lo) + __popc(m0hi & lm);
    const int dn_hi = __popc(m1lo) + __popc(m1hi & lm);

    const int s_hi = lane + 32;
    // Store uint4-unit row base (row * 8) to save the shift in the hot loop.
    s_base[w][lane] = (unsigned)((i0 * TRI + loff(lane) + u_lo * (lane + 1) + dn_lo) * 8);
    s_base[w][s_hi] = (unsigned)((i1 * TRI + loff(s_hi) + u_hi * (s_hi + 1) + dn_hi) * 8);
    __syncwarp();

    // ---- vectorized log-sum ----
    const int o = lane & 7;        // m-octet: m = 8o .. 8o+7
    const int g = lane >> 3;       // site group: sites 4k + g
    const uint4* __restrict__ vec = (const uint4*)g_scratch2;

    float2 a0 = {0.f, 0.f}, a1 = {0.f, 0.f}, a2 = {0.f, 0.f}, a3 = {0.f, 0.f};
    #pragma unroll
    for (int k = 0; k < 16; ++k) {
        const uint4 v = vec[s_base[w][4 * k + g] + o];
        const float2 f0 = __half22float2(*(const __half2*)&v.x);
        const float2 f1 = __half22float2(*(const __half2*)&v.y);
        const float2 f2 = __half22float2(*(const __half2*)&v.z);
        const float2 f3 = __half22float2(*(const __half2*)&v.w);
        a0.x += f0.x; a0.y += f0.y;
        a1.x += f1.x; a1.y += f1.y;
        a2.x += f2.x; a2.y += f2.y;
        a3.x += f3.x; a3.y += f3.y;
    }

    // Reduce over the 4 site groups (lanes o, o+8, o+16, o+24): xor 8, 16.
    #pragma unroll
    for (int off = 8; off <= 16; off <<= 1) {
        a0.x += __shfl_xor_sync(0xffffffffu, a0.x, off);
        a0.y += __shfl_xor_sync(0xffffffffu, a0.y, off);
        a1.x += __shfl_xor_sync(0xffffffffu, a1.x, off);
        a1.y += __shfl_xor_sync(0xffffffffu, a1.y, off);
        a2.x += __shfl_xor_sync(0xffffffffu, a2.x, off);
        a2.y += __shfl_xor_sync(0xffffffffu, a2.y, off);
        a3.x += __shfl_xor_sync(0xffffffffu, a3.x, off);
        a3.y += __shfl_xor_sync(0xffffffffu, a3.y, off);
    }

    // Per-lane: sum of the 8 m-products of octet o, then butterfly over octets.
    float p = (exp2f(a0.x) + exp2f(a0.y)) + (exp2f(a1.x) + exp2f(a1.y))
            + (exp2f(a2.x) + exp2f(a2.y)) + (exp2f(a3.x) + exp2f(a3.y));
    p += __shfl_xor_sync(0xffffffffu, p, 1);
    p += __shfl_xor_sync(0xffffffffu, p, 2);
    p += __shfl_xor_sync(0xffffffffu, p, 4);

    if (lane == 0) out[b] = p;
}

// ---------------------------------------------------------------------------
extern "C" void kernel_launch(void* const* d_in, const int* in_sizes, int n_in,
                              void* d_out, int out_size) {
    const float* eps = (const float*)d_in[1];
    float*       out = (float*)d_out;

    mark_partial <<<NGROUP, 256>>>(d_in[0]);
    reduce_rng   <<<64, 256>>>();
    eps_transpose<<<dim3(64, 32, 4), dim3(32, 8)>>>(eps);
    seggps_compute<<<8192 / 8, 256>>>(d_in[0], out);
}